// round 8
// baseline (speedup 1.0000x reference)
#include <cuda_runtime.h>

// Problem constants (fixed: B=16, T=1024, D=1024, O=10)
#define BB 16
#define TT 1024
#define DD 1024
#define OO 10

#define CTA 256
#define WARPS 8
#define RPW 4                     // rows per warp (scalar acc = 40 regs)
#define RPC (WARPS * RPW)         // 32 rows per CTA
#define KT 128                    // d per iteration (4 floats per lane)
#define NKT (DD / KT)             // 8
#define W_FLOATS (OO * DD)        // 10240 floats = 40 KB static smem

__device__ float g_scores[BB * OO * TT];   // [b][o][t]
__device__ float g_wx[BB * OO * TT];       // softmaxed, [b][o][i]

// ---------------------------------------------------------------------------
// GEMV body: 4 rows x 1024 d (per warp) against Wsm (10 x 1024 in smem).
// Scalar FMA, distance-1 float4 prefetch (8 LDG.128 in flight per warp).
// ---------------------------------------------------------------------------
__device__ __forceinline__ void gemv_body(const float* __restrict__ rbase,
                                          const float* __restrict__ wbase,
                                          float (&acc)[RPW][OO]) {
    #pragma unroll
    for (int r = 0; r < RPW; r++)
        #pragma unroll
        for (int o = 0; o < OO; o++) acc[r][o] = 0.0f;

    float4 cur[RPW], nxt[RPW];
    #pragma unroll
    for (int r = 0; r < RPW; r++)
        cur[r] = *(const float4*)(rbase + r * DD);

    #pragma unroll
    for (int kt = 0; kt < NKT; kt++) {
        if (kt + 1 < NKT) {
            #pragma unroll
            for (int r = 0; r < RPW; r++)
                nxt[r] = *(const float4*)(rbase + r * DD + (kt + 1) * KT);
        }
        #pragma unroll
        for (int o = 0; o < OO; o++) {
            const float4 w4 = *(const float4*)(wbase + o * DD + kt * KT);
            #pragma unroll
            for (int r = 0; r < RPW; r++) {
                acc[r][o] = fmaf(cur[r].x, w4.x, acc[r][o]);
                acc[r][o] = fmaf(cur[r].y, w4.y, acc[r][o]);
                acc[r][o] = fmaf(cur[r].z, w4.z, acc[r][o]);
                acc[r][o] = fmaf(cur[r].w, w4.w, acc[r][o]);
            }
        }
        #pragma unroll
        for (int r = 0; r < RPW; r++) cur[r] = nxt[r];
    }
}

// Reduce 40 partials across warp; lane0 writes [o][t]-layout results.
__device__ __forceinline__ void reduce_store(float (&acc)[RPW][OO], int lane,
                                             float* __restrict__ dst,
                                             int t0, float scale,
                                             const float* __restrict__ bias) {
    #pragma unroll
    for (int r = 0; r < RPW; r++)
        #pragma unroll
        for (int o = 0; o < OO; o++) {
            float v = acc[r][o];
            #pragma unroll
            for (int s = 16; s > 0; s >>= 1)
                v += __shfl_xor_sync(0xffffffffu, v, s);
            if (lane == 0) {
                if (bias) v = (v + __ldg(&bias[o])) * scale;
                dst[o * TT + t0 + r] = v;
            }
        }
}

// ---------------------------------------------------------------------------
// Kernel 1: scores[b][o][t] = (logits[b,t,:] . W[o,:] + bias[o]) / OO
// Grid 512 x 256; 32 rows/CTA; 3 CTAs/SM.
// ---------------------------------------------------------------------------
__global__ __launch_bounds__(CTA, 3) void k_scores(const float* __restrict__ logits,
                                                   const float* __restrict__ W,
                                                   const float* __restrict__ bias) {
    __shared__ float Wsm[W_FLOATS];   // 40 KB static
    {
        const float4* Wv = (const float4*)W;
        float4* Ws = (float4*)Wsm;
        #pragma unroll
        for (int t = 0; t < 10; t++)
            Ws[threadIdx.x + t * CTA] = Wv[threadIdx.x + t * CTA];
    }
    __syncthreads();

    const int warp = threadIdx.x >> 5;
    const int lane = threadIdx.x & 31;
    const int row0 = blockIdx.x * RPC + warp * RPW;

    float acc[RPW][OO];
    gemv_body(logits + (size_t)row0 * DD + lane * 4, Wsm + lane * 4, acc);

    const int b = row0 / TT;
    reduce_store(acc, lane, g_scores + b * OO * TT, row0 % TT, 1.0f / OO, bias);
}

// ---------------------------------------------------------------------------
// Kernel 2: softmax over t for each (b,o). 160 blocks x 256 threads.
// ---------------------------------------------------------------------------
__global__ __launch_bounds__(256) void k_softmax() {
    const int ro = blockIdx.x;
    const int tid = threadIdx.x;
    const float4 v = ((const float4*)&g_scores[ro * TT])[tid];

    __shared__ float red[8];

    float m = fmaxf(fmaxf(v.x, v.y), fmaxf(v.z, v.w));
    #pragma unroll
    for (int s = 16; s > 0; s >>= 1)
        m = fmaxf(m, __shfl_xor_sync(0xffffffffu, m, s));
    if ((tid & 31) == 0) red[tid >> 5] = m;
    __syncthreads();
    float mall = red[0];
    #pragma unroll
    for (int i = 1; i < 8; i++) mall = fmaxf(mall, red[i]);
    __syncthreads();

    float4 e;
    e.x = __expf(v.x - mall);
    e.y = __expf(v.y - mall);
    e.z = __expf(v.z - mall);
    e.w = __expf(v.w - mall);
    float s4 = e.x + e.y + e.z + e.w;
    #pragma unroll
    for (int s = 16; s > 0; s >>= 1)
        s4 += __shfl_xor_sync(0xffffffffu, s4, s);
    if ((tid & 31) == 0) red[tid >> 5] = s4;
    __syncthreads();
    float sall = 0.0f;
    #pragma unroll
    for (int i = 0; i < 8; i++) sall += red[i];

    const float inv = 1.0f / sall;
    float4 w;
    w.x = e.x * inv; w.y = e.y * inv; w.z = e.z * inv; w.w = e.w * inv;
    ((float4*)&g_wx[ro * TT])[tid] = w;
}

// ---------------------------------------------------------------------------
// Kernel 3: out[b][o][t] = sum_i logits[b,t,i] * g_wx[b][o][i]
// Grid walked in REVERSE so the first wave reads rows k_scores touched last
// (still L2-resident).
// ---------------------------------------------------------------------------
__global__ __launch_bounds__(CTA, 3) void k_out(const float* __restrict__ logits,
                                                float* __restrict__ out) {
    __shared__ float Wsm[W_FLOATS];

    const int blk = gridDim.x - 1 - blockIdx.x;      // reverse order
    const int row0blk = blk * RPC;
    const int b = row0blk / TT;                      // 32 rows never cross a batch
    {
        const float4* Wv = (const float4*)(g_wx + (size_t)b * W_FLOATS);
        float4* Ws = (float4*)Wsm;
        #pragma unroll
        for (int t = 0; t < 10; t++)
            Ws[threadIdx.x + t * CTA] = Wv[threadIdx.x + t * CTA];
    }
    __syncthreads();

    const int warp = threadIdx.x >> 5;
    const int lane = threadIdx.x & 31;
    const int row0 = row0blk + warp * RPW;

    float acc[RPW][OO];
    gemv_body(logits + (size_t)row0 * DD + lane * 4, Wsm + lane * 4, acc);

    reduce_store(acc, lane, out + b * OO * TT, row0 % TT, 1.0f, nullptr);
}

// ---------------------------------------------------------------------------
// Launch: inputs per metadata order: logits, decision(unused), W, b
// ---------------------------------------------------------------------------
extern "C" void kernel_launch(void* const* d_in, const int* in_sizes, int n_in,
                              void* d_out, int out_size) {
    const float* logits = (const float*)d_in[0];
    const float* W = (const float*)d_in[2];
    const float* bias = (const float*)d_in[3];
    float* out = (float*)d_out;

    k_scores<<<(BB * TT) / RPC, CTA>>>(logits, W, bias);
    k_softmax<<<BB * OO, 256>>>();
    k_out<<<(BB * TT) / RPC, CTA>>>(logits, out);
}

// round 9
// speedup vs baseline: 1.0484x; 1.0484x over previous
#include <cuda_runtime.h>

// Problem constants (fixed: B=16, T=1024, D=1024, O=10)
#define BB 16
#define TT 1024
#define DD 1024
#define OO 10

#define CTA 256
#define WARPS 8
#define RPW 4                     // rows per warp (acc = 40 scalar regs)
#define RPC 16                    // rows per CTA (8 warps = 4 rowgroups x 2 halves)
#define KT 128                    // d per chunk (4 floats per lane)
#define NCH 4                     // chunks per half-row (512 floats)
#define HALF 512
#define W_FLOATS (OO * DD)        // 10240 floats = 40 KB static smem

__device__ float g_scores[BB * OO * TT];   // [b][o][t]

// ---------------------------------------------------------------------------
// Half-row GEMV: warp covers 4 rows x 512 d. All 16 LDG.128 issued up-front
// (64 data regs in flight), then consumed against Wsm via LDS.128.
// rbase/wbase already offset by half*512 + lane*4.
// ---------------------------------------------------------------------------
__device__ __forceinline__ void gemv_half(const float* __restrict__ rbase,
                                          const float* __restrict__ wbase,
                                          float (&acc)[RPW][OO]) {
    float4 v[NCH][RPW];
    #pragma unroll
    for (int kt = 0; kt < NCH; kt++)
        #pragma unroll
        for (int r = 0; r < RPW; r++)
            v[kt][r] = *(const float4*)(rbase + r * DD + kt * KT);

    #pragma unroll
    for (int r = 0; r < RPW; r++)
        #pragma unroll
        for (int o = 0; o < OO; o++) acc[r][o] = 0.0f;

    #pragma unroll
    for (int kt = 0; kt < NCH; kt++)
        #pragma unroll
        for (int o = 0; o < OO; o++) {
            const float4 w4 = *(const float4*)(wbase + o * DD + kt * KT);
            #pragma unroll
            for (int r = 0; r < RPW; r++) {
                acc[r][o] = fmaf(v[kt][r].x, w4.x, acc[r][o]);
                acc[r][o] = fmaf(v[kt][r].y, w4.y, acc[r][o]);
                acc[r][o] = fmaf(v[kt][r].z, w4.z, acc[r][o]);
                acc[r][o] = fmaf(v[kt][r].w, w4.w, acc[r][o]);
            }
        }
}

// Warp-reduce 40 partials; lane0 deposits into partial[warp][0..39].
__device__ __forceinline__ void warp_deposit(float (&acc)[RPW][OO], int warp,
                                             int lane, float (*partial)[40]) {
    #pragma unroll
    for (int r = 0; r < RPW; r++)
        #pragma unroll
        for (int o = 0; o < OO; o++) {
            float x = acc[r][o];
            #pragma unroll
            for (int s = 16; s > 0; s >>= 1)
                x += __shfl_xor_sync(0xffffffffu, x, s);
            if (lane == 0) partial[warp][r * OO + o] = x;
        }
}

// ---------------------------------------------------------------------------
// Kernel 1: scores[b][o][t] = (logits[b,t,:] . W[o,:] + bias[o]) / OO
// Grid 1024 x 256; 16 rows/CTA; warp = (rowgroup, half).
// ---------------------------------------------------------------------------
__global__ __launch_bounds__(CTA, 2) void k_scores(const float* __restrict__ logits,
                                                   const float* __restrict__ W,
                                                   const float* __restrict__ bias) {
    __shared__ float Wsm[W_FLOATS];            // 40 KB
    __shared__ float partial[WARPS][40];
    {
        const float4* Wv = (const float4*)W;
        float4* Ws = (float4*)Wsm;
        #pragma unroll
        for (int t = 0; t < 10; t++)
            Ws[threadIdx.x + t * CTA] = Wv[threadIdx.x + t * CTA];
    }
    __syncthreads();

    const int warp = threadIdx.x >> 5;
    const int lane = threadIdx.x & 31;
    const int rg = warp >> 1;                  // rowgroup 0..3
    const int h = warp & 1;                    // half 0..1
    const int row0 = blockIdx.x * RPC + rg * RPW;
    const int doff = h * HALF + lane * 4;

    float acc[RPW][OO];
    gemv_half(logits + (size_t)row0 * DD + doff, Wsm + doff, acc);
    warp_deposit(acc, warp, lane, partial);
    __syncthreads();

    if (threadIdx.x < 160) {
        const int rg2 = threadIdx.x / 40;
        const int idx = threadIdx.x % 40;
        const int r = idx / OO, o = idx % OO;
        const float v = partial[rg2 * 2][idx] + partial[rg2 * 2 + 1][idx];
        const int row = blockIdx.x * RPC + rg2 * RPW + r;
        const int b = row / TT, t = row % TT;
        g_scores[(b * OO + o) * TT + t] = (v + __ldg(&bias[o])) * (1.0f / OO);
    }
}

// ---------------------------------------------------------------------------
// Kernel 2 (fused softmax + output):
//   Wsm <- scores[b]; softmax each of the 10 rows over t in-place;
//   out[b][o][t] = sum_i logits[b,t,i] * Wsm[o][i]
// Grid walked in reverse (L2 reuse of rows k_scores touched last).
// ---------------------------------------------------------------------------
__global__ __launch_bounds__(CTA, 2) void k_out(const float* __restrict__ logits,
                                                float* __restrict__ out) {
    __shared__ float Wsm[W_FLOATS];
    __shared__ float partial[WARPS][40];

    const int blk = gridDim.x - 1 - blockIdx.x;
    const int row0blk = blk * RPC;
    const int b = row0blk / TT;                // 16 rows never cross a batch

    {
        const float4* Sv = (const float4*)(g_scores + (size_t)b * W_FLOATS);
        float4* Ws = (float4*)Wsm;
        #pragma unroll
        for (int t = 0; t < 10; t++)
            Ws[threadIdx.x + t * CTA] = Sv[threadIdx.x + t * CTA];
    }
    __syncthreads();

    const int warp = threadIdx.x >> 5;
    const int lane = threadIdx.x & 31;

    // In-place softmax over each of the 10 rows (length 1024).
    for (int o = warp; o < OO; o += WARPS) {
        float* row = Wsm + o * DD;
        float m = -3.0e38f;
        #pragma unroll
        for (int i = 0; i < DD / 32; i++)
            m = fmaxf(m, row[lane + i * 32]);
        #pragma unroll
        for (int s = 16; s > 0; s >>= 1)
            m = fmaxf(m, __shfl_xor_sync(0xffffffffu, m, s));
        float sum = 0.0f;
        #pragma unroll
        for (int i = 0; i < DD / 32; i++) {
            const float e = __expf(row[lane + i * 32] - m);
            row[lane + i * 32] = e;
            sum += e;
        }
        #pragma unroll
        for (int s = 16; s > 0; s >>= 1)
            sum += __shfl_xor_sync(0xffffffffu, sum, s);
        const float inv = 1.0f / sum;
        #pragma unroll
        for (int i = 0; i < DD / 32; i++)
            row[lane + i * 32] *= inv;
    }
    __syncthreads();

    const int rg = warp >> 1;
    const int h = warp & 1;
    const int row0 = row0blk + rg * RPW;
    const int doff = h * HALF + lane * 4;

    float acc[RPW][OO];
    gemv_half(logits + (size_t)row0 * DD + doff, Wsm + doff, acc);
    warp_deposit(acc, warp, lane, partial);
    __syncthreads();

    if (threadIdx.x < 160) {
        const int rg2 = threadIdx.x / 40;
        const int idx = threadIdx.x % 40;
        const int r = idx / OO, o = idx % OO;
        const float v = partial[rg2 * 2][idx] + partial[rg2 * 2 + 1][idx];
        const int row = row0blk + rg2 * RPW + r;
        const int t = row % TT;
        out[(b * OO + o) * TT + t] = v;
    }
}

// ---------------------------------------------------------------------------
// Launch: inputs per metadata order: logits, decision(unused), W, b
// ---------------------------------------------------------------------------
extern "C" void kernel_launch(void* const* d_in, const int* in_sizes, int n_in,
                              void* d_out, int out_size) {
    const float* logits = (const float*)d_in[0];
    const float* W = (const float*)d_in[2];
    const float* bias = (const float*)d_in[3];
    float* out = (float*)d_out;

    k_scores<<<(BB * TT) / RPC, CTA>>>(logits, W, bias);
    k_out<<<(BB * TT) / RPC, CTA>>>(logits, out);
}

// round 10
// speedup vs baseline: 1.1396x; 1.0870x over previous
#include <cuda_runtime.h>

// Problem constants (fixed: B=16, T=1024, D=1024, O=10)
#define BB 16
#define TT 1024
#define DD 1024
#define OO 10

#define CTA 256
#define WARPS 8
#define RPW 4                     // rows per warp (acc = 40 scalar regs)
#define RPC 16                    // rows per CTA (4 rowgroups x 2 d-halves)
#define KT 128                    // d per chunk (4 floats per lane)
#define NCH 4                     // chunks per half-row (512 floats)
#define HALF 512
#define W_FLOATS (OO * DD)        // 10240 floats = 40 KB static smem

__device__ float g_scores[BB * OO * TT];   // [b][o][t]
__device__ float g_wx[BB * OO * TT];       // softmaxed, [b][o][i]

// ---------------------------------------------------------------------------
// Half-row GEMV: warp covers 4 rows x 512 d. All 16 LDG.128 issued up-front
// (64 data regs in flight), then consumed against Wsm via LDS.128.
// rbase/wbase already offset by half*512 + lane*4.
// ---------------------------------------------------------------------------
__device__ __forceinline__ void gemv_half(const float* __restrict__ rbase,
                                          const float* __restrict__ wbase,
                                          float (&acc)[RPW][OO]) {
    float4 v[NCH][RPW];
    #pragma unroll
    for (int kt = 0; kt < NCH; kt++)
        #pragma unroll
        for (int r = 0; r < RPW; r++)
            v[kt][r] = *(const float4*)(rbase + r * DD + kt * KT);

    #pragma unroll
    for (int r = 0; r < RPW; r++)
        #pragma unroll
        for (int o = 0; o < OO; o++) acc[r][o] = 0.0f;

    #pragma unroll
    for (int kt = 0; kt < NCH; kt++)
        #pragma unroll
        for (int o = 0; o < OO; o++) {
            const float4 w4 = *(const float4*)(wbase + o * DD + kt * KT);
            #pragma unroll
            for (int r = 0; r < RPW; r++) {
                acc[r][o] = fmaf(v[kt][r].x, w4.x, acc[r][o]);
                acc[r][o] = fmaf(v[kt][r].y, w4.y, acc[r][o]);
                acc[r][o] = fmaf(v[kt][r].z, w4.z, acc[r][o]);
                acc[r][o] = fmaf(v[kt][r].w, w4.w, acc[r][o]);
            }
        }
}

// Warp-reduce 40 partials; lane0 deposits into partial[warp][0..39].
__device__ __forceinline__ void warp_deposit(float (&acc)[RPW][OO], int warp,
                                             int lane, float (*partial)[40]) {
    #pragma unroll
    for (int r = 0; r < RPW; r++)
        #pragma unroll
        for (int o = 0; o < OO; o++) {
            float x = acc[r][o];
            #pragma unroll
            for (int s = 16; s > 0; s >>= 1)
                x += __shfl_xor_sync(0xffffffffu, x, s);
            if (lane == 0) partial[warp][r * OO + o] = x;
        }
}

// ---------------------------------------------------------------------------
// Kernel 1: scores[b][o][t] = (logits[b,t,:] . W[o,:] + bias[o]) / OO
// Grid 1024 x 256; 16 rows/CTA; warp = (rowgroup, half).  [R9-proven: ~17.5us]
// ---------------------------------------------------------------------------
__global__ __launch_bounds__(CTA, 2) void k_scores(const float* __restrict__ logits,
                                                   const float* __restrict__ W,
                                                   const float* __restrict__ bias) {
    __shared__ float Wsm[W_FLOATS];            // 40 KB
    __shared__ float partial[WARPS][40];
    {
        const float4* Wv = (const float4*)W;
        float4* Ws = (float4*)Wsm;
        #pragma unroll
        for (int t = 0; t < 10; t++)
            Ws[threadIdx.x + t * CTA] = Wv[threadIdx.x + t * CTA];
    }
    __syncthreads();

    const int warp = threadIdx.x >> 5;
    const int lane = threadIdx.x & 31;
    const int rg = warp >> 1;                  // rowgroup 0..3
    const int h = warp & 1;                    // half 0..1
    const int row0 = blockIdx.x * RPC + rg * RPW;
    const int doff = h * HALF + lane * 4;

    float acc[RPW][OO];
    gemv_half(logits + (size_t)row0 * DD + doff, Wsm + doff, acc);
    warp_deposit(acc, warp, lane, partial);
    __syncthreads();

    if (threadIdx.x < 160) {
        const int rg2 = threadIdx.x / 40;
        const int idx = threadIdx.x % 40;
        const int r = idx / OO, o = idx % OO;
        const float v = partial[rg2 * 2][idx] + partial[rg2 * 2 + 1][idx];
        const int row = blockIdx.x * RPC + rg2 * RPW + r;
        const int b = row / TT, t = row % TT;
        g_scores[(b * OO + o) * TT + t] = (v + __ldg(&bias[o])) * (1.0f / OO);
    }
}

// ---------------------------------------------------------------------------
// Kernel 2: softmax over t for each (b,o). 160 blocks x 256 threads.
// ---------------------------------------------------------------------------
__global__ __launch_bounds__(256) void k_softmax() {
    const int ro = blockIdx.x;
    const int tid = threadIdx.x;
    const float4 v = ((const float4*)&g_scores[ro * TT])[tid];

    __shared__ float red[8];

    float m = fmaxf(fmaxf(v.x, v.y), fmaxf(v.z, v.w));
    #pragma unroll
    for (int s = 16; s > 0; s >>= 1)
        m = fmaxf(m, __shfl_xor_sync(0xffffffffu, m, s));
    if ((tid & 31) == 0) red[tid >> 5] = m;
    __syncthreads();
    float mall = red[0];
    #pragma unroll
    for (int i = 1; i < 8; i++) mall = fmaxf(mall, red[i]);
    __syncthreads();

    float4 e;
    e.x = __expf(v.x - mall);
    e.y = __expf(v.y - mall);
    e.z = __expf(v.z - mall);
    e.w = __expf(v.w - mall);
    float s4 = e.x + e.y + e.z + e.w;
    #pragma unroll
    for (int s = 16; s > 0; s >>= 1)
        s4 += __shfl_xor_sync(0xffffffffu, s4, s);
    if ((tid & 31) == 0) red[tid >> 5] = s4;
    __syncthreads();
    float sall = 0.0f;
    #pragma unroll
    for (int i = 0; i < 8; i++) sall += red[i];

    const float inv = 1.0f / sall;
    float4 w;
    w.x = e.x * inv; w.y = e.y * inv; w.z = e.z * inv; w.w = e.w * inv;
    ((float4*)&g_wx[ro * TT])[tid] = w;
}

// ---------------------------------------------------------------------------
// Kernel 3: out[b][o][t] = sum_i logits[b,t,i] * g_wx[b][o][i]
// Identical lean gemv as k_scores (no softmax state, no spills); L2-fed.
// ---------------------------------------------------------------------------
__global__ __launch_bounds__(CTA, 2) void k_out(const float* __restrict__ logits,
                                                float* __restrict__ out) {
    __shared__ float Wsm[W_FLOATS];
    __shared__ float partial[WARPS][40];

    const int row0blk = blockIdx.x * RPC;
    const int b = row0blk / TT;                // 16 rows never cross a batch
    {
        const float4* Wv = (const float4*)(g_wx + (size_t)b * W_FLOATS);
        float4* Ws = (float4*)Wsm;
        #pragma unroll
        for (int t = 0; t < 10; t++)
            Ws[threadIdx.x + t * CTA] = Wv[threadIdx.x + t * CTA];
    }
    __syncthreads();

    const int warp = threadIdx.x >> 5;
    const int lane = threadIdx.x & 31;
    const int rg = warp >> 1;
    const int h = warp & 1;
    const int row0 = row0blk + rg * RPW;
    const int doff = h * HALF + lane * 4;

    float acc[RPW][OO];
    gemv_half(logits + (size_t)row0 * DD + doff, Wsm + doff, acc);
    warp_deposit(acc, warp, lane, partial);
    __syncthreads();

    if (threadIdx.x < 160) {
        const int rg2 = threadIdx.x / 40;
        const int idx = threadIdx.x % 40;
        const int r = idx / OO, o = idx % OO;
        const float v = partial[rg2 * 2][idx] + partial[rg2 * 2 + 1][idx];
        const int row = row0blk + rg2 * RPW + r;
        const int t = row % TT;
        out[(b * OO + o) * TT + t] = v;
    }
}

// ---------------------------------------------------------------------------
// Launch: inputs per metadata order: logits, decision(unused), W, b
// ---------------------------------------------------------------------------
extern "C" void kernel_launch(void* const* d_in, const int* in_sizes, int n_in,
                              void* d_out, int out_size) {
    const float* logits = (const float*)d_in[0];
    const float* W = (const float*)d_in[2];
    const float* bias = (const float*)d_in[3];
    float* out = (float*)d_out;

    k_scores<<<(BB * TT) / RPC, CTA>>>(logits, W, bias);
    k_softmax<<<BB * OO, 256>>>();
    k_out<<<(BB * TT) / RPC, CTA>>>(logits, out);
}

// round 11
// speedup vs baseline: 1.1463x; 1.0059x over previous
#include <cuda_runtime.h>

// Problem constants (fixed: B=16, T=1024, D=1024, O=10)
#define BB 16
#define TT 1024
#define DD 1024
#define OO 10

#define CTA 256
#define WARPS 8
#define RPW 4                     // full rows per warp (acc = 40 scalar regs)
#define RPC (WARPS * RPW)         // 32 rows per CTA
#define KT 128                    // d per chunk (4 floats per lane)
#define NKT (DD / KT)             // 8 chunks per row
#define PIPE 3                    // register pipeline depth (48 regs)
#define W_FLOATS (OO * DD)        // 10240 floats = 40 KB static smem

__device__ float g_scores[BB * OO * TT];   // [b][o][t]
__device__ float g_wx[BB * OO * TT];       // softmaxed, [b][o][i]

// ---------------------------------------------------------------------------
// Pipelined GEMV: warp covers 4 rows x 1024 d. 3-deep register buffer keeps
// 8-12 LDG.128 outstanding CONTINUOUSLY while FMA consumes chunk kt.
// rbase/wbase already offset by lane*4.
// ---------------------------------------------------------------------------
__device__ __forceinline__ void gemv_rows(const float* __restrict__ rbase,
                                          const float* __restrict__ wbase,
                                          float (&acc)[RPW][OO]) {
    float4 buf[PIPE][RPW];

    #pragma unroll
    for (int p = 0; p < PIPE; p++)
        #pragma unroll
        for (int r = 0; r < RPW; r++)
            buf[p][r] = *(const float4*)(rbase + r * DD + p * KT);

    #pragma unroll
    for (int r = 0; r < RPW; r++)
        #pragma unroll
        for (int o = 0; o < OO; o++) acc[r][o] = 0.0f;

    #pragma unroll
    for (int kt = 0; kt < NKT; kt++) {
        const int cur = kt % PIPE;

        #pragma unroll
        for (int o = 0; o < OO; o++) {
            const float4 w4 = *(const float4*)(wbase + o * DD + kt * KT);
            #pragma unroll
            for (int r = 0; r < RPW; r++) {
                acc[r][o] = fmaf(buf[cur][r].x, w4.x, acc[r][o]);
                acc[r][o] = fmaf(buf[cur][r].y, w4.y, acc[r][o]);
                acc[r][o] = fmaf(buf[cur][r].z, w4.z, acc[r][o]);
                acc[r][o] = fmaf(buf[cur][r].w, w4.w, acc[r][o]);
            }
        }

        if (kt + PIPE < NKT) {
            #pragma unroll
            for (int r = 0; r < RPW; r++)
                buf[cur][r] = *(const float4*)(rbase + r * DD + (kt + PIPE) * KT);
        }
    }
}

// Reduce 40 partials across warp; lane0 writes [o][t]-layout results.
__device__ __forceinline__ void reduce_store(float (&acc)[RPW][OO], int lane,
                                             float* __restrict__ dst,
                                             int t0, float scale,
                                             const float* __restrict__ bias) {
    #pragma unroll
    for (int r = 0; r < RPW; r++)
        #pragma unroll
        for (int o = 0; o < OO; o++) {
            float v = acc[r][o];
            #pragma unroll
            for (int s = 16; s > 0; s >>= 1)
                v += __shfl_xor_sync(0xffffffffu, v, s);
            if (lane == 0) {
                if (bias) v = (v + __ldg(&bias[o])) * scale;
                dst[o * TT + t0 + r] = v;
            }
        }
}

// ---------------------------------------------------------------------------
// Kernel 1: scores[b][o][t] = (logits[b,t,:] . W[o,:] + bias[o]) / OO
// Grid 512 x 256; 32 rows/CTA.
// ---------------------------------------------------------------------------
__global__ __launch_bounds__(CTA, 2) void k_scores(const float* __restrict__ logits,
                                                   const float* __restrict__ W,
                                                   const float* __restrict__ bias) {
    __shared__ float Wsm[W_FLOATS];   // 40 KB static
    {
        const float4* Wv = (const float4*)W;
        float4* Ws = (float4*)Wsm;
        #pragma unroll
        for (int t = 0; t < 10; t++)
            Ws[threadIdx.x + t * CTA] = Wv[threadIdx.x + t * CTA];
    }
    __syncthreads();

    const int warp = threadIdx.x >> 5;
    const int lane = threadIdx.x & 31;
    const int row0 = blockIdx.x * RPC + warp * RPW;

    float acc[RPW][OO];
    gemv_rows(logits + (size_t)row0 * DD + lane * 4, Wsm + lane * 4, acc);

    const int b = row0 / TT;
    reduce_store(acc, lane, g_scores + b * OO * TT, row0 % TT, 1.0f / OO, bias);
}

// ---------------------------------------------------------------------------
// Kernel 2: softmax over t for each (b,o). 160 blocks x 256 threads.
// ---------------------------------------------------------------------------
__global__ __launch_bounds__(256) void k_softmax() {
    const int ro = blockIdx.x;
    const int tid = threadIdx.x;
    const float4 v = ((const float4*)&g_scores[ro * TT])[tid];

    __shared__ float red[8];

    float m = fmaxf(fmaxf(v.x, v.y), fmaxf(v.z, v.w));
    #pragma unroll
    for (int s = 16; s > 0; s >>= 1)
        m = fmaxf(m, __shfl_xor_sync(0xffffffffu, m, s));
    if ((tid & 31) == 0) red[tid >> 5] = m;
    __syncthreads();
    float mall = red[0];
    #pragma unroll
    for (int i = 1; i < 8; i++) mall = fmaxf(mall, red[i]);
    __syncthreads();

    float4 e;
    e.x = __expf(v.x - mall);
    e.y = __expf(v.y - mall);
    e.z = __expf(v.z - mall);
    e.w = __expf(v.w - mall);
    float s4 = e.x + e.y + e.z + e.w;
    #pragma unroll
    for (int s = 16; s > 0; s >>= 1)
        s4 += __shfl_xor_sync(0xffffffffu, s4, s);
    if ((tid & 31) == 0) red[tid >> 5] = s4;
    __syncthreads();
    float sall = 0.0f;
    #pragma unroll
    for (int i = 0; i < 8; i++) sall += red[i];

    const float inv = 1.0f / sall;
    float4 w;
    w.x = e.x * inv; w.y = e.y * inv; w.z = e.z * inv; w.w = e.w * inv;
    ((float4*)&g_wx[ro * TT])[tid] = w;
}

// ---------------------------------------------------------------------------
// Kernel 3: out[b][o][t] = sum_i logits[b,t,i] * g_wx[b][o][i]
// Same lean pipelined gemv; logits reads are L2-resident after pass 1.
// ---------------------------------------------------------------------------
__global__ __launch_bounds__(CTA, 2) void k_out(const float* __restrict__ logits,
                                                float* __restrict__ out) {
    __shared__ float Wsm[W_FLOATS];

    const int row0blk = blockIdx.x * RPC;
    const int b = row0blk / TT;               // 32 rows never cross a batch
    {
        const float4* Wv = (const float4*)(g_wx + (size_t)b * W_FLOATS);
        float4* Ws = (float4*)Wsm;
        #pragma unroll
        for (int t = 0; t < 10; t++)
            Ws[threadIdx.x + t * CTA] = Wv[threadIdx.x + t * CTA];
    }
    __syncthreads();

    const int warp = threadIdx.x >> 5;
    const int lane = threadIdx.x & 31;
    const int row0 = row0blk + warp * RPW;

    float acc[RPW][OO];
    gemv_rows(logits + (size_t)row0 * DD + lane * 4, Wsm + lane * 4, acc);

    reduce_store(acc, lane, out + b * OO * TT, row0 % TT, 1.0f, nullptr);
}

// ---------------------------------------------------------------------------
// Launch: inputs per metadata order: logits, decision(unused), W, b
// ---------------------------------------------------------------------------
extern "C" void kernel_launch(void* const* d_in, const int* in_sizes, int n_in,
                              void* d_out, int out_size) {
    const float* logits = (const float*)d_in[0];
    const float* W = (const float*)d_in[2];
    const float* bias = (const float*)d_in[3];
    float* out = (float*)d_out;

    k_scores<<<(BB * TT) / RPC, CTA>>>(logits, W, bias);
    k_softmax<<<BB * OO, 256>>>();
    k_out<<<(BB * TT) / RPC, CTA>>>(logits, out);
}